// round 16
// baseline (speedup 1.0000x reference)
#include <cuda_runtime.h>
#include <cuda_fp16.h>
#include <string.h>
#include <math.h>

#define HH 960
#define WW 1280
#define NPIX (HH*WW)
#define HUBER_Bf 0.02f
#define L_RGBf 1e-6f
#define DAMPINGf 0.001f
#define ACC_GRID (NPIX / (256 * 4))

// ---- half2 <-> uint bit casts ----
__device__ __forceinline__ unsigned int h2_as_u(__half2 h) {
    unsigned int u; memcpy(&u, &h, 4); return u;
}
__device__ __forceinline__ __half2 u_as_h2(unsigned int u) {
    __half2 h; memcpy(&h, &u, 4); return h;
}

// ---------------- scratch ----------------
__device__ uint4        g_nmx[NPIX];     // halfs nx,ny | nz,r | fp32 depth | halfs g,b
__device__ uint4        g_pack[NPIX];    // halfs: gx0,gx1 | gx2,gy0 | gy1,gy2 | P,Q
__device__ double       g_acc[3][27];
__device__ double       g_rgbTot[21];
__device__ float        g_pose[16];
__device__ unsigned int g_ticket[3];
__device__ unsigned int g_dmin = 0x7f800000u;
__device__ unsigned int g_dmax = 0u;

__device__ __forceinline__ void make_warp_jac(float dirx, float diry, float invD,
                                              float fx, float fy,
                                              float* Jx, float* Jy) {
    Jx[0] = -dirx * diry * fx;        Jy[0] = -(1.f + diry * diry) * fy;
    Jx[1] = (1.f + dirx * dirx) * fx; Jy[1] = dirx * diry * fy;
    Jx[2] = -diry * fx;               Jy[2] = dirx * fy;
    Jx[3] = invD * fx;                Jy[3] = 0.f;
    Jx[4] = 0.f;                      Jy[4] = invD * fy;
    Jx[5] = -dirx * invD * fx;        Jy[5] = -diry * invD * fy;
}

// ---------------- min/max of depth1 + per-replay resets ----------------
__global__ void k_minmax(const float* __restrict__ d1, const float* __restrict__ pose_in) {
    if (blockIdx.x == 0) {
        int t = threadIdx.x;
        if (t < 16) g_pose[t] = pose_in[t];
        if (t >= 32 && t < 53) g_rgbTot[t - 32] = 0.0;
        if (t >= 64 && t < 67) g_ticket[t - 64] = 0u;
    }
    int i = blockIdx.x * blockDim.x + threadIdx.x;
    int stride = gridDim.x * blockDim.x;
    float mn = 3.4e38f, mx = 0.f;
    const float4* p = (const float4*)d1;
    for (int k = i; k < NPIX / 4; k += stride) {
        float4 v = p[k];
        mn = fminf(mn, fminf(fminf(v.x, v.y), fminf(v.z, v.w)));
        mx = fmaxf(mx, fmaxf(fmaxf(v.x, v.y), fmaxf(v.z, v.w)));
    }
    #pragma unroll
    for (int o = 16; o > 0; o >>= 1) {
        mn = fminf(mn, __shfl_down_sync(0xffffffffu, mn, o));
        mx = fmaxf(mx, __shfl_down_sync(0xffffffffu, mx, o));
    }
    if ((threadIdx.x & 31) == 0) {
        atomicMin(&g_dmin, __float_as_uint(mn));
        atomicMax(&g_dmax, __float_as_uint(mx));
    }
}

// ---------------- fused precompute: 4 consecutive px / thread, reg-reused stencils ----
__global__ void __launch_bounds__(256)
k_pre(const float* __restrict__ d0, const float* __restrict__ d1,
      const float* __restrict__ x0, const float* __restrict__ x1,
      const float* __restrict__ Km) {
    float fx = Km[0], fy = Km[4], cx = Km[2], cy = Km[5];
    float ifx = 1.f / fx, ify = 1.f / fy;

    float tw[21];
    #pragma unroll
    for (int i = 0; i < 21; i++) tw[i] = 0.f;

    int base = (blockIdx.x * blockDim.x + threadIdx.x) * 4;
    {
        int r = base / WW, c0 = base - r * WW;
        int rr[3] = {max(r - 1, 0), r, min(r + 1, HH - 1)};
        int rowB[3] = {rr[0] * WW, rr[1] * WW, rr[2] * WW};
        float rrf[3] = {(float)rr[0], (float)rr[1], (float)rr[2]};
        int cc[6];
        cc[0] = max(c0 - 1, 0);
        cc[1] = c0; cc[2] = c0 + 1; cc[3] = c0 + 2; cc[4] = c0 + 3;
        cc[5] = min(c0 + 4, WW - 1);
        float ccf[6];
        #pragma unroll
        for (int j = 0; j < 6; j++) ccf[j] = (float)cc[j];

        float D[3][6];
        #pragma unroll
        for (int a = 0; a < 3; a++)
            #pragma unroll
            for (int j = 0; j < 6; j++)
                D[a][j] = d1[rowB[a] + cc[j]];

        float x1v[12];
        {
            const float4* xp = (const float4*)(x1 + base * 3);
            float4 q0 = xp[0], q1 = xp[1], q2 = xp[2];
            x1v[0]=q0.x; x1v[1]=q0.y; x1v[2]=q0.z; x1v[3]=q0.w;
            x1v[4]=q1.x; x1v[5]=q1.y; x1v[6]=q1.z; x1v[7]=q1.w;
            x1v[8]=q2.x; x1v[9]=q2.y; x1v[10]=q2.z; x1v[11]=q2.w;
        }
        float4 d0v4 = *(const float4*)(d0 + base);
        float dmin = __uint_as_float(g_dmin), dmax = __uint_as_float(g_dmax);

        #pragma unroll
        for (int i = 0; i < 4; i++) {
            float dx[3], dy[3];
            #pragma unroll
            for (int k = 0; k < 3; k++) {
                float v00, v02, v10, v12, v20, v22, v01, v21;
                #define VTX(a,j) (k == 0 ? (ccf[j] - cx) * ifx * D[a][j] \
                                : k == 1 ? (rrf[a] - cy) * ify * D[a][j] : D[a][j])
                v00 = VTX(0, i);     v02 = VTX(0, i + 2);
                v10 = VTX(1, i);     v12 = VTX(1, i + 2);
                v20 = VTX(2, i);     v22 = VTX(2, i + 2);
                v01 = VTX(0, i + 1); v21 = VTX(2, i + 1);
                #undef VTX
                dx[k] = (v02 - v00) + 2.f * (v12 - v10) + (v22 - v20);
                dy[k] = (v20 - v00) + 2.f * (v21 - v01) + (v22 - v02);
            }
            float nx = dx[1] * dy[2] - dx[2] * dy[1];
            float ny = dx[2] * dy[0] - dx[0] * dy[2];
            float nz = dx[0] * dy[1] - dx[1] * dy[0];
            float nrm = sqrtf(nx * nx + ny * ny + nz * nz) + 1e-8f;
            nx /= nrm; ny /= nrm; nz /= nrm;
            float dctr = D[1][i + 1];
            if (dctr <= dmin || dctr >= dmax) { nx = 0.f; ny = 0.f; nz = 0.f; }
            uint4 o;
            o.x = h2_as_u(__floats2half2_rn(nx, ny));
            o.y = h2_as_u(__floats2half2_rn(nz, x1v[i * 3]));
            o.z = __float_as_uint(dctr);
            o.w = h2_as_u(__floats2half2_rn(x1v[i * 3 + 1], x1v[i * 3 + 2]));
            g_nmx[base + i] = o;
        }

        float gx[4][3], gy[4][3], P[4] = {0.f,0.f,0.f,0.f}, Q[4] = {0.f,0.f,0.f,0.f};
        #pragma unroll
        for (int ch = 0; ch < 3; ch++) {
            float X[3][6];
            #pragma unroll
            for (int a = 0; a < 3; a++)
                #pragma unroll
                for (int j = 0; j < 6; j++)
                    X[a][j] = x0[(rowB[a] + cc[j]) * 3 + ch];
            #pragma unroll
            for (int i = 0; i < 4; i++) {
                float sdx = (X[0][i+2] - X[0][i]) + 2.f * (X[1][i+2] - X[1][i]) + (X[2][i+2] - X[2][i]);
                float sdy = (X[2][i] - X[0][i]) + 2.f * (X[2][i+1] - X[0][i+1]) + (X[2][i+2] - X[0][i+2]);
                float mag = sqrtf(sdx * sdx + sdy * sdy + 1e-8f);
                float g1 = __half2float(__float2half_rn(sdx / mag));
                float g2 = __half2float(__float2half_rn(sdy / mag));
                gx[i][ch] = g1; gy[i][ch] = g2;
                P[i] += g1 * X[1][i + 1];
                Q[i] += g2 * X[1][i + 1];
            }
        }
        #pragma unroll
        for (int i = 0; i < 4; i++) {
            uint4 o;
            o.x = h2_as_u(__floats2half2_rn(gx[i][0], gx[i][1]));
            o.y = h2_as_u(__floats2half2_rn(gx[i][2], gy[i][0]));
            o.z = h2_as_u(__floats2half2_rn(gy[i][1], gy[i][2]));
            o.w = h2_as_u(__floats2half2_rn(P[i], Q[i]));
            g_pack[base + i] = o;
        }

        #pragma unroll
        for (int i = 0; i < 4; i++) {
            float d0v = (&d0v4.x)[i];
            if (d0v > 0.f) {
                float dirx = (ccf[i + 1] - cx) * ifx;
                float diry = ((float)r - cy) * ify;
                float invD = __fdividef(1.f, d0v);
                float Jx[6], Jy[6];
                make_warp_jac(dirx, diry, invD, fx, fy, Jx, Jy);
                float A = gx[i][0]*gx[i][0] + gx[i][1]*gx[i][1] + gx[i][2]*gx[i][2];
                float B = gx[i][0]*gy[i][0] + gx[i][1]*gy[i][1] + gx[i][2]*gy[i][2];
                float C = gy[i][0]*gy[i][0] + gy[i][1]*gy[i][1] + gy[i][2]*gy[i][2];
                int o = 0;
                #pragma unroll
                for (int a = 0; a < 6; a++)
                    #pragma unroll
                    for (int b = a; b < 6; b++)
                        tw[o++] += A * Jx[a] * Jx[b] + B * (Jx[a] * Jy[b] + Jy[a] * Jx[b]) + C * Jy[a] * Jy[b];
            }
        }
    }

    __shared__ float sred[21][9];
    int lane = threadIdx.x & 31, wid = threadIdx.x >> 5;
    #pragma unroll
    for (int i = 0; i < 21; i++) {
        float v = tw[i];
        #pragma unroll
        for (int o = 16; o > 0; o >>= 1) v += __shfl_down_sync(0xffffffffu, v, o);
        if (lane == 0) sred[i][wid] = v;
    }
    __syncthreads();
    if (threadIdx.x < 21) {
        float s = 0.f;
        #pragma unroll
        for (int w = 0; w < 8; w++) s += sred[threadIdx.x][w];
        atomicAdd(&g_rgbTot[threadIdx.x], (double)s);
    }
}

// ---------------- 6x6 solve + SE(3) update (device fn, 1 thread, fp32) ----------------
__device__ void do_solve(int iter, float* __restrict__ outp) {
    double* ac = g_acc[iter];
    float M[6][7];
    int o = 0;
    for (int i = 0; i < 6; i++)
        for (int j = i; j < 6; j++) {
            float v = (float)(ac[o] + (double)L_RGBf * g_rgbTot[o]);
            M[i][j] = v; M[j][i] = v; o++;
        }
    for (int i = 0; i < 6; i++) M[i][6] = (float)ac[21 + i];
    for (int i = 0; i < 27; i++) ac[i] = 0.0;

    float tr = 0.f;
    for (int i = 0; i < 6; i++) tr += M[i][i];
    for (int i = 0; i < 6; i++) M[i][i] += tr * DAMPINGf;

    #pragma unroll
    for (int k = 0; k < 6; k++) {
        int piv = k; float mx = fabsf(M[k][k]);
        #pragma unroll
        for (int i2 = k + 1; i2 < 6; i2++) {
            float a = fabsf(M[i2][k]);
            if (a > mx) { mx = a; piv = i2; }
        }
        if (piv != k)
            #pragma unroll
            for (int j = 0; j < 7; j++) { float t = M[k][j]; M[k][j] = M[piv][j]; M[piv][j] = t; }
        float id = 1.f / M[k][k];
        #pragma unroll
        for (int i2 = k + 1; i2 < 6; i2++) {
            float f = M[i2][k] * id;
            #pragma unroll
            for (int j = k; j < 7; j++) M[i2][j] -= f * M[k][j];
        }
    }
    float xi[6];
    #pragma unroll
    for (int i = 5; i >= 0; i--) {
        float s = M[i][6];
        #pragma unroll
        for (int j = 0; j < 6; j++) if (j > i) s -= M[i][j] * xi[j];
        xi[i] = s / M[i][i];
    }

    float w0 = -xi[0], w1 = -xi[1], w2 = -xi[2];
    float th2 = fmaxf(w0 * w0 + w1 * w1 + w2 * w2, 1e-30f);
    float th = sqrtf(th2);
    float dR[3][3] = {{1.f,0.f,0.f},{0.f,1.f,0.f},{0.f,0.f,1.f}};
    if (th > 1e-10f) {
        float A = sinf(th) / th;
        float B = (1.f - cosf(th)) / th2;
        float Wm[3][3] = {{0.f, -w2, w1}, {w2, 0.f, -w0}, {-w1, w0, 0.f}};
        float W2[3][3];
        #pragma unroll
        for (int i = 0; i < 3; i++)
            #pragma unroll
            for (int j = 0; j < 3; j++)
                W2[i][j] = Wm[i][0] * Wm[0][j] + Wm[i][1] * Wm[1][j] + Wm[i][2] * Wm[2][j];
        #pragma unroll
        for (int i = 0; i < 3; i++)
            #pragma unroll
            for (int j = 0; j < 3; j++)
                dR[i][j] = (i == j ? 1.f : 0.f) + A * Wm[i][j] + B * W2[i][j];
    }
    float dt[3];
    #pragma unroll
    for (int i = 0; i < 3; i++)
        dt[i] = -(dR[i][0] * xi[3] + dR[i][1] * xi[4] + dR[i][2] * xi[5]);

    float R0[3][3], t0[3];
    #pragma unroll
    for (int i = 0; i < 3; i++) {
        #pragma unroll
        for (int j = 0; j < 3; j++) R0[i][j] = g_pose[i * 4 + j];
        t0[i] = g_pose[i * 4 + 3];
    }
    float R1[3][3], t1[3];
    #pragma unroll
    for (int i = 0; i < 3; i++) {
        #pragma unroll
        for (int j = 0; j < 3; j++)
            R1[i][j] = dR[i][0] * R0[0][j] + dR[i][1] * R0[1][j] + dR[i][2] * R0[2][j];
        t1[i] = dR[i][0] * t0[0] + dR[i][1] * t0[1] + dR[i][2] * t0[2] + dt[i];
    }
    #pragma unroll
    for (int i = 0; i < 3; i++) {
        #pragma unroll
        for (int j = 0; j < 3; j++) g_pose[i * 4 + j] = R1[i][j];
        g_pose[i * 4 + 3] = t1[i];
    }
    if (iter == 2) {
        for (int i = 0; i < 16; i++) outp[i] = g_pose[i];
    }
}

// ---- streaming bilinear corner accumulation ----
struct Blend {
    float nwx, nwy, nwz;
    float w1r, w1g, w1b;
    float s0, s1d, t0, t1;
};
__device__ __forceinline__ void blend_corner(Blend& B, const uint4 q, float w,
                                             bool col0, bool row0) {
    float2 axy = __half22float2(u_as_h2(q.x));
    float2 ezr = __half22float2(u_as_h2(q.y));
    float  d   = __uint_as_float(q.z);
    float2 gb  = __half22float2(u_as_h2(q.w));
    B.nwx += w * axy.x;  B.nwy += w * axy.y;  B.nwz += w * ezr.x;
    B.w1r += w * ezr.y;  B.w1g += w * gb.x;   B.w1b += w * gb.y;
    float wd = w * d;
    if (col0) B.s0 += wd; else B.s1d += wd;
    if (row0) B.t0 += wd; else B.t1 += wd;
}

// per-pixel accumulation tail (pk already decoded, gathers already in q00..q11)
__device__ __forceinline__ void accum_pixel(
    float* acc, bool inview,
    float tx, float ty, float tz, float uu, float vv, float u0f, float v0f,
    uint4 q00, uint4 q01, uint4 q10, uint4 q11,
    float2 h0, float2 h1, float2 h2, float2 h3,
    const float* Jx, const float* Jy,
    float fx, float fy, float cx, float cy, float ifx, float ify)
{
    if (!inview) {
        float A = h0.x * h0.x + h0.y * h0.y + h1.x * h1.x;
        float B = h0.x * h1.y + h0.y * h2.x + h1.x * h2.y;
        float C = h1.y * h1.y + h2.x * h2.x + h2.y * h2.y;
        int o = 0;
        #pragma unroll
        for (int i = 0; i < 6; i++)
            #pragma unroll
            for (int j = i; j < 6; j++) {
                acc[o] -= L_RGBf * (A * Jx[i] * Jx[j] + B * (Jx[i] * Jy[j] + Jy[i] * Jx[j]) + C * Jy[i] * Jy[j]);
                o++;
            }
        return;
    }
    float wu = uu - u0f, wv = vv - v0f;
    float w00 = (1.f - wu) * (1.f - wv), w01 = wu * (1.f - wv);
    float w10 = (1.f - wu) * wv,        w11 = wu * wv;

    Blend B = {0.f,0.f,0.f, 0.f,0.f,0.f, 0.f,0.f,0.f,0.f};
    blend_corner(B, q00, w00, true,  true);
    blend_corner(B, q01, w01, false, true);
    blend_corner(B, q10, w10, true,  false);
    blend_corner(B, q11, w11, false, false);

    float v1z = B.s0 + B.s1d;
    float v1x = (B.s0 * (u0f - cx) + B.s1d * (u0f + 1.f - cx)) * ifx;
    float v1y = (B.t0 * (v0f - cy) + B.t1 * (v0f + 1.f - cy)) * ify;
    float dfx = tx - v1x, dfy = ty - v1y, dfz = tz - v1z;
    float dist2 = dfx * dfx + dfy * dfy + dfz * dfz;
    if (v1z > 0.f && dist2 < 0.01f) {
        float res = B.nwx * dfx + B.nwy * dfy + B.nwz * dfz;
        float J[6];
        J[0] = ty * B.nwz - tz * B.nwy;
        J[1] = tz * B.nwx - tx * B.nwz;
        J[2] = tx * B.nwy - ty * B.nwx;
        J[3] = B.nwx; J[4] = B.nwy; J[5] = B.nwz;
        float ax = fabsf(res);
        float rho = (ax <= HUBER_Bf) ? ax * ax : 2.f * HUBER_Bf * ax - HUBER_Bf * HUBER_Bf;
        float xs = (ax < 1e-8f) ? 1.f : ax;
        float w = sqrtf(rho + 1e-16f) / xs;
        float w2 = w * w;
        int o = 0;
        #pragma unroll
        for (int i = 0; i < 6; i++) {
            float wi = w2 * J[i];
            #pragma unroll
            for (int j = i; j < 6; j++) acc[o++] += wi * J[j];
        }
        #pragma unroll
        for (int i = 0; i < 6; i++) acc[21 + i] += w2 * J[i] * res;
    }
    float a = L_RGBf * (h0.x * B.w1r + h0.y * B.w1g + h1.x * B.w1b - h3.x);
    float b = L_RGBf * (h1.y * B.w1r + h2.x * B.w1g + h2.y * B.w1b - h3.y);
    #pragma unroll
    for (int i = 0; i < 6; i++) acc[21 + i] += a * Jx[i] + b * Jy[i];
}

// ---- fused ICP + RGB accumulation: 2-pixel pairs, fully unconditional gathers -------
__global__ void __launch_bounds__(256, 2)
k_accum(const float* __restrict__ d0, const float* __restrict__ Km, int iter,
        float* __restrict__ outp) {
    float fx = Km[0], fy = Km[4], cx = Km[2], cy = Km[5];
    float ifx = 1.f / fx, ify = 1.f / fy;
    float p00 = g_pose[0],  p01 = g_pose[1],  p02 = g_pose[2],  p03 = g_pose[3];
    float p10 = g_pose[4],  p11 = g_pose[5],  p12 = g_pose[6],  p13 = g_pose[7];
    float p20 = g_pose[8],  p21 = g_pose[9],  p22 = g_pose[10], p23 = g_pose[11];

    float acc[27];
    #pragma unroll
    for (int i = 0; i < 27; i++) acc[i] = 0.f;

    int lane = threadIdx.x & 31;
    int warpGlobal = (blockIdx.x * blockDim.x + threadIdx.x) >> 5;
    int pbase = warpGlobal * 128;            // 1280 % 128 == 0: warp block in one row
    {
        int r = pbase / WW;
        int cw = pbase - r * WW;
        float diry = ((float)r - cy) * ify;

        float dv[4];
        #pragma unroll
        for (int k = 0; k < 4; k++)
            dv[k] = d0[r * WW + cw + lane + 32 * k];

        #pragma unroll
        for (int hlf = 0; hlf < 2; hlf++) {
            int kA = hlf * 2, kB = kA + 1;
            int cA = cw + lane + 32 * kA;
            int cB = cA + 32;
            int idxA = r * WW + cA, idxB = idxA + 32;
            float dA = dv[kA], dB = dv[kB];
            bool mA = dA > 0.f, mB = dB > 0.f;
            if (!mA && !mB) continue;

            uint4 pkA = g_pack[idxA];
            uint4 pkB = g_pack[idxB];

            // --- projections (both pixels; NaN/inf tolerated when masked) ---
            float dirxA = ((float)cA - cx) * ifx;
            float dirxB = ((float)cB - cx) * ifx;
            float txA = p00 * (dirxA * dA) + p01 * (diry * dA) + p02 * dA + p03;
            float tyA = p10 * (dirxA * dA) + p11 * (diry * dA) + p12 * dA + p13;
            float tzA = p20 * (dirxA * dA) + p21 * (diry * dA) + p22 * dA + p23;
            float txB = p00 * (dirxB * dB) + p01 * (diry * dB) + p02 * dB + p03;
            float tyB = p10 * (dirxB * dB) + p11 * (diry * dB) + p12 * dB + p13;
            float tzB = p20 * (dirxB * dB) + p21 * (diry * dB) + p22 * dB + p23;
            float invzA = __fdividef(1.f, tzA), invzB = __fdividef(1.f, tzB);
            float uuA = txA * invzA * fx + cx, vvA = tyA * invzA * fy + cy;
            float uuB = txB * invzB * fx + cx, vvB = tyB * invzB * fy + cy;
            bool inA = (uuA > 0.f) && (uuA < (float)(WW-1)) && (vvA > 0.f) && (vvA < (float)(HH-1)) && (tzA > 0.f);
            bool inB = (uuB > 0.f) && (uuB < (float)(WW-1)) && (vvB > 0.f) && (vvB < (float)(HH-1)) && (tzB > 0.f);

            // NaN-safe clamps -> unconditional gather addresses
            float u0fA = floorf(fminf(fmaxf(uuA, 0.f), (float)(WW-2)));
            float v0fA = floorf(fminf(fmaxf(vvA, 0.f), (float)(HH-2)));
            float u0fB = floorf(fminf(fmaxf(uuB, 0.f), (float)(WW-2)));
            float v0fB = floorf(fminf(fmaxf(vvB, 0.f), (float)(HH-2)));
            int iA00 = (int)v0fA * WW + (int)u0fA, iA10 = iA00 + WW;
            int iB00 = (int)v0fB * WW + (int)u0fB, iB10 = iB00 + WW;

            // --- all 8 gathers issued back-to-back ---
            uint4 qA00 = g_nmx[iA00], qA01 = g_nmx[iA00 + 1];
            uint4 qA10 = g_nmx[iA10], qA11 = g_nmx[iA10 + 1];
            uint4 qB00 = g_nmx[iB00], qB01 = g_nmx[iB00 + 1];
            uint4 qB10 = g_nmx[iB10], qB11 = g_nmx[iB10 + 1];

            // --- overlap: decode + jacobians while gathers are in flight ---
            float JxA[6], JyA[6], JxB[6], JyB[6];
            make_warp_jac(dirxA, diry, __fdividef(1.f, dA), fx, fy, JxA, JyA);
            make_warp_jac(dirxB, diry, __fdividef(1.f, dB), fx, fy, JxB, JyB);
            float2 hA0 = __half22float2(u_as_h2(pkA.x));
            float2 hA1 = __half22float2(u_as_h2(pkA.y));
            float2 hA2 = __half22float2(u_as_h2(pkA.z));
            float2 hA3 = __half22float2(u_as_h2(pkA.w));
            float2 hB0 = __half22float2(u_as_h2(pkB.x));
            float2 hB1 = __half22float2(u_as_h2(pkB.y));
            float2 hB2 = __half22float2(u_as_h2(pkB.z));
            float2 hB3 = __half22float2(u_as_h2(pkB.w));

            if (mA) accum_pixel(acc, inA, txA, tyA, tzA, uuA, vvA, u0fA, v0fA,
                                qA00, qA01, qA10, qA11, hA0, hA1, hA2, hA3,
                                JxA, JyA, fx, fy, cx, cy, ifx, ify);
            if (mB) accum_pixel(acc, inB, txB, tyB, tzB, uuB, vvB, u0fB, v0fB,
                                qB00, qB01, qB10, qB11, hB0, hB1, hB2, hB3,
                                JxB, JyB, fx, fy, cx, cy, ifx, ify);
        }
    }

    __shared__ float sred[27][9];
    int wid = threadIdx.x >> 5;
    #pragma unroll
    for (int i = 0; i < 27; i++) {
        float v = acc[i];
        #pragma unroll
        for (int o = 16; o > 0; o >>= 1) v += __shfl_down_sync(0xffffffffu, v, o);
        if (lane == 0) sred[i][wid] = v;
    }
    __syncthreads();
    if (threadIdx.x < 27) {
        float s = 0.f;
        #pragma unroll
        for (int w = 0; w < 8; w++) s += sred[threadIdx.x][w];
        atomicAdd(&g_acc[iter][threadIdx.x], (double)s);
    }

    // ---- last-block-does-solve ----
    __shared__ bool isLast;
    __syncthreads();
    if (threadIdx.x == 0) {
        __threadfence();
        unsigned int v = atomicAdd(&g_ticket[iter], 1u);
        isLast = (v == (unsigned int)(gridDim.x - 1));
    }
    __syncthreads();
    if (isLast && threadIdx.x == 0) {
        __threadfence();
        do_solve(iter, outp);
    }
}

// ---------------- launch ----------------
extern "C" void kernel_launch(void* const* d_in, const int* in_sizes, int n_in,
                              void* d_out, int out_size) {
    const float* pose10 = (const float*)d_in[0];
    const float* depth0 = (const float*)d_in[1];
    const float* depth1 = (const float*)d_in[2];
    const float* x0     = (const float*)d_in[3];
    const float* x1     = (const float*)d_in[4];
    const float* Km     = (const float*)d_in[5];
    float* out = (float*)d_out;

    k_minmax<<<512, 256>>>(depth1, pose10);
    k_pre<<<NPIX / (256 * 4), 256>>>(depth0, depth1, x0, x1, Km);
    for (int it = 0; it < 3; it++)
        k_accum<<<ACC_GRID, 256>>>(depth0, Km, it, out);
}

// round 17
// speedup vs baseline: 1.0669x; 1.0669x over previous
#include <cuda_runtime.h>
#include <cuda_fp16.h>
#include <string.h>
#include <math.h>

#define HH 960
#define WW 1280
#define NPIX (HH*WW)
#define HUBER_Bf 0.02f
#define L_RGBf 1e-6f
#define DAMPINGf 0.001f
#define ACC_BLOCKS 444          // 148 SMs x 3 CTAs: single full wave
#define NCHUNKS (NPIX / 128)    // 9600 warp-chunks of 128 px

// ---- half2 <-> uint bit casts ----
__device__ __forceinline__ unsigned int h2_as_u(__half2 h) {
    unsigned int u; memcpy(&u, &h, 4); return u;
}
__device__ __forceinline__ __half2 u_as_h2(unsigned int u) {
    __half2 h; memcpy(&h, &u, 4); return h;
}

// ---------------- scratch ----------------
__device__ uint4        g_nmx[NPIX];     // halfs nx,ny | nz,r | fp32 depth | halfs g,b
__device__ uint4        g_pack[NPIX];    // halfs: gx0,gx1 | gx2,gy0 | gy1,gy2 | P,Q
__device__ double       g_acc[3][27];
__device__ double       g_rgbTot[21];
__device__ float        g_pose[16];
__device__ unsigned int g_ticket[3];
__device__ unsigned int g_dmin = 0x7f800000u;
__device__ unsigned int g_dmax = 0u;

__device__ __forceinline__ void make_warp_jac(float dirx, float diry, float invD,
                                              float fx, float fy,
                                              float* Jx, float* Jy) {
    Jx[0] = -dirx * diry * fx;        Jy[0] = -(1.f + diry * diry) * fy;
    Jx[1] = (1.f + dirx * dirx) * fx; Jy[1] = dirx * diry * fy;
    Jx[2] = -diry * fx;               Jy[2] = dirx * fy;
    Jx[3] = invD * fx;                Jy[3] = 0.f;
    Jx[4] = 0.f;                      Jy[4] = invD * fy;
    Jx[5] = -dirx * invD * fx;        Jy[5] = -diry * invD * fy;
}

// ---------------- min/max of depth1 + per-replay resets ----------------
__global__ void k_minmax(const float* __restrict__ d1, const float* __restrict__ pose_in) {
    if (blockIdx.x == 0) {
        int t = threadIdx.x;
        if (t < 16) g_pose[t] = pose_in[t];
        if (t >= 32 && t < 53) g_rgbTot[t - 32] = 0.0;
        if (t >= 64 && t < 67) g_ticket[t - 64] = 0u;
    }
    int i = blockIdx.x * blockDim.x + threadIdx.x;
    int stride = gridDim.x * blockDim.x;
    float mn = 3.4e38f, mx = 0.f;
    const float4* p = (const float4*)d1;
    for (int k = i; k < NPIX / 4; k += stride) {
        float4 v = p[k];
        mn = fminf(mn, fminf(fminf(v.x, v.y), fminf(v.z, v.w)));
        mx = fmaxf(mx, fmaxf(fmaxf(v.x, v.y), fmaxf(v.z, v.w)));
    }
    #pragma unroll
    for (int o = 16; o > 0; o >>= 1) {
        mn = fminf(mn, __shfl_down_sync(0xffffffffu, mn, o));
        mx = fmaxf(mx, __shfl_down_sync(0xffffffffu, mx, o));
    }
    if ((threadIdx.x & 31) == 0) {
        atomicMin(&g_dmin, __float_as_uint(mn));
        atomicMax(&g_dmax, __float_as_uint(mx));
    }
}

// ---------------- fused precompute: 4 consecutive px / thread, reg-reused stencils ----
__global__ void __launch_bounds__(256)
k_pre(const float* __restrict__ d0, const float* __restrict__ d1,
      const float* __restrict__ x0, const float* __restrict__ x1,
      const float* __restrict__ Km) {
    float fx = Km[0], fy = Km[4], cx = Km[2], cy = Km[5];
    float ifx = 1.f / fx, ify = 1.f / fy;

    float tw[21];
    #pragma unroll
    for (int i = 0; i < 21; i++) tw[i] = 0.f;

    int base = (blockIdx.x * blockDim.x + threadIdx.x) * 4;
    {
        int r = base / WW, c0 = base - r * WW;
        int rr[3] = {max(r - 1, 0), r, min(r + 1, HH - 1)};
        int rowB[3] = {rr[0] * WW, rr[1] * WW, rr[2] * WW};
        float rrf[3] = {(float)rr[0], (float)rr[1], (float)rr[2]};
        int cc[6];
        cc[0] = max(c0 - 1, 0);
        cc[1] = c0; cc[2] = c0 + 1; cc[3] = c0 + 2; cc[4] = c0 + 3;
        cc[5] = min(c0 + 4, WW - 1);
        float ccf[6];
        #pragma unroll
        for (int j = 0; j < 6; j++) ccf[j] = (float)cc[j];

        float D[3][6];
        #pragma unroll
        for (int a = 0; a < 3; a++)
            #pragma unroll
            for (int j = 0; j < 6; j++)
                D[a][j] = d1[rowB[a] + cc[j]];

        float x1v[12];
        {
            const float4* xp = (const float4*)(x1 + base * 3);
            float4 q0 = xp[0], q1 = xp[1], q2 = xp[2];
            x1v[0]=q0.x; x1v[1]=q0.y; x1v[2]=q0.z; x1v[3]=q0.w;
            x1v[4]=q1.x; x1v[5]=q1.y; x1v[6]=q1.z; x1v[7]=q1.w;
            x1v[8]=q2.x; x1v[9]=q2.y; x1v[10]=q2.z; x1v[11]=q2.w;
        }
        float4 d0v4 = *(const float4*)(d0 + base);
        float dmin = __uint_as_float(g_dmin), dmax = __uint_as_float(g_dmax);

        #pragma unroll
        for (int i = 0; i < 4; i++) {
            float dx[3], dy[3];
            #pragma unroll
            for (int k = 0; k < 3; k++) {
                float v00, v02, v10, v12, v20, v22, v01, v21;
                #define VTX(a,j) (k == 0 ? (ccf[j] - cx) * ifx * D[a][j] \
                                : k == 1 ? (rrf[a] - cy) * ify * D[a][j] : D[a][j])
                v00 = VTX(0, i);     v02 = VTX(0, i + 2);
                v10 = VTX(1, i);     v12 = VTX(1, i + 2);
                v20 = VTX(2, i);     v22 = VTX(2, i + 2);
                v01 = VTX(0, i + 1); v21 = VTX(2, i + 1);
                #undef VTX
                dx[k] = (v02 - v00) + 2.f * (v12 - v10) + (v22 - v20);
                dy[k] = (v20 - v00) + 2.f * (v21 - v01) + (v22 - v02);
            }
            float nx = dx[1] * dy[2] - dx[2] * dy[1];
            float ny = dx[2] * dy[0] - dx[0] * dy[2];
            float nz = dx[0] * dy[1] - dx[1] * dy[0];
            float nrm = sqrtf(nx * nx + ny * ny + nz * nz) + 1e-8f;
            nx /= nrm; ny /= nrm; nz /= nrm;
            float dctr = D[1][i + 1];
            if (dctr <= dmin || dctr >= dmax) { nx = 0.f; ny = 0.f; nz = 0.f; }
            uint4 o;
            o.x = h2_as_u(__floats2half2_rn(nx, ny));
            o.y = h2_as_u(__floats2half2_rn(nz, x1v[i * 3]));
            o.z = __float_as_uint(dctr);
            o.w = h2_as_u(__floats2half2_rn(x1v[i * 3 + 1], x1v[i * 3 + 2]));
            g_nmx[base + i] = o;
        }

        float gx[4][3], gy[4][3], P[4] = {0.f,0.f,0.f,0.f}, Q[4] = {0.f,0.f,0.f,0.f};
        #pragma unroll
        for (int ch = 0; ch < 3; ch++) {
            float X[3][6];
            #pragma unroll
            for (int a = 0; a < 3; a++)
                #pragma unroll
                for (int j = 0; j < 6; j++)
                    X[a][j] = x0[(rowB[a] + cc[j]) * 3 + ch];
            #pragma unroll
            for (int i = 0; i < 4; i++) {
                float sdx = (X[0][i+2] - X[0][i]) + 2.f * (X[1][i+2] - X[1][i]) + (X[2][i+2] - X[2][i]);
                float sdy = (X[2][i] - X[0][i]) + 2.f * (X[2][i+1] - X[0][i+1]) + (X[2][i+2] - X[0][i+2]);
                float mag = sqrtf(sdx * sdx + sdy * sdy + 1e-8f);
                float g1 = __half2float(__float2half_rn(sdx / mag));
                float g2 = __half2float(__float2half_rn(sdy / mag));
                gx[i][ch] = g1; gy[i][ch] = g2;
                P[i] += g1 * X[1][i + 1];
                Q[i] += g2 * X[1][i + 1];
            }
        }
        #pragma unroll
        for (int i = 0; i < 4; i++) {
            uint4 o;
            o.x = h2_as_u(__floats2half2_rn(gx[i][0], gx[i][1]));
            o.y = h2_as_u(__floats2half2_rn(gx[i][2], gy[i][0]));
            o.z = h2_as_u(__floats2half2_rn(gy[i][1], gy[i][2]));
            o.w = h2_as_u(__floats2half2_rn(P[i], Q[i]));
            g_pack[base + i] = o;
        }

        #pragma unroll
        for (int i = 0; i < 4; i++) {
            float d0v = (&d0v4.x)[i];
            if (d0v > 0.f) {
                float dirx = (ccf[i + 1] - cx) * ifx;
                float diry = ((float)r - cy) * ify;
                float invD = __fdividef(1.f, d0v);
                float Jx[6], Jy[6];
                make_warp_jac(dirx, diry, invD, fx, fy, Jx, Jy);
                float A = gx[i][0]*gx[i][0] + gx[i][1]*gx[i][1] + gx[i][2]*gx[i][2];
                float B = gx[i][0]*gy[i][0] + gx[i][1]*gy[i][1] + gx[i][2]*gy[i][2];
                float C = gy[i][0]*gy[i][0] + gy[i][1]*gy[i][1] + gy[i][2]*gy[i][2];
                int o = 0;
                #pragma unroll
                for (int a = 0; a < 6; a++)
                    #pragma unroll
                    for (int b = a; b < 6; b++)
                        tw[o++] += A * Jx[a] * Jx[b] + B * (Jx[a] * Jy[b] + Jy[a] * Jx[b]) + C * Jy[a] * Jy[b];
            }
        }
    }

    __shared__ float sred[21][9];
    int lane = threadIdx.x & 31, wid = threadIdx.x >> 5;
    #pragma unroll
    for (int i = 0; i < 21; i++) {
        float v = tw[i];
        #pragma unroll
        for (int o = 16; o > 0; o >>= 1) v += __shfl_down_sync(0xffffffffu, v, o);
        if (lane == 0) sred[i][wid] = v;
    }
    __syncthreads();
    if (threadIdx.x < 21) {
        float s = 0.f;
        #pragma unroll
        for (int w = 0; w < 8; w++) s += sred[threadIdx.x][w];
        atomicAdd(&g_rgbTot[threadIdx.x], (double)s);
    }
}

// ---------------- 6x6 solve + SE(3) update (device fn, 1 thread, fp32) ----------------
__device__ void do_solve(int iter, float* __restrict__ outp) {
    double* ac = g_acc[iter];
    float M[6][7];
    int o = 0;
    for (int i = 0; i < 6; i++)
        for (int j = i; j < 6; j++) {
            float v = (float)(ac[o] + (double)L_RGBf * g_rgbTot[o]);
            M[i][j] = v; M[j][i] = v; o++;
        }
    for (int i = 0; i < 6; i++) M[i][6] = (float)ac[21 + i];
    for (int i = 0; i < 27; i++) ac[i] = 0.0;

    float tr = 0.f;
    for (int i = 0; i < 6; i++) tr += M[i][i];
    for (int i = 0; i < 6; i++) M[i][i] += tr * DAMPINGf;

    #pragma unroll
    for (int k = 0; k < 6; k++) {
        int piv = k; float mx = fabsf(M[k][k]);
        #pragma unroll
        for (int i2 = k + 1; i2 < 6; i2++) {
            float a = fabsf(M[i2][k]);
            if (a > mx) { mx = a; piv = i2; }
        }
        if (piv != k)
            #pragma unroll
            for (int j = 0; j < 7; j++) { float t = M[k][j]; M[k][j] = M[piv][j]; M[piv][j] = t; }
        float id = 1.f / M[k][k];
        #pragma unroll
        for (int i2 = k + 1; i2 < 6; i2++) {
            float f = M[i2][k] * id;
            #pragma unroll
            for (int j = k; j < 7; j++) M[i2][j] -= f * M[k][j];
        }
    }
    float xi[6];
    #pragma unroll
    for (int i = 5; i >= 0; i--) {
        float s = M[i][6];
        #pragma unroll
        for (int j = 0; j < 6; j++) if (j > i) s -= M[i][j] * xi[j];
        xi[i] = s / M[i][i];
    }

    float w0 = -xi[0], w1 = -xi[1], w2 = -xi[2];
    float th2 = fmaxf(w0 * w0 + w1 * w1 + w2 * w2, 1e-30f);
    float th = sqrtf(th2);
    float dR[3][3] = {{1.f,0.f,0.f},{0.f,1.f,0.f},{0.f,0.f,1.f}};
    if (th > 1e-10f) {
        float A = sinf(th) / th;
        float B = (1.f - cosf(th)) / th2;
        float Wm[3][3] = {{0.f, -w2, w1}, {w2, 0.f, -w0}, {-w1, w0, 0.f}};
        float W2[3][3];
        #pragma unroll
        for (int i = 0; i < 3; i++)
            #pragma unroll
            for (int j = 0; j < 3; j++)
                W2[i][j] = Wm[i][0] * Wm[0][j] + Wm[i][1] * Wm[1][j] + Wm[i][2] * Wm[2][j];
        #pragma unroll
        for (int i = 0; i < 3; i++)
            #pragma unroll
            for (int j = 0; j < 3; j++)
                dR[i][j] = (i == j ? 1.f : 0.f) + A * Wm[i][j] + B * W2[i][j];
    }
    float dt[3];
    #pragma unroll
    for (int i = 0; i < 3; i++)
        dt[i] = -(dR[i][0] * xi[3] + dR[i][1] * xi[4] + dR[i][2] * xi[5]);

    float R0[3][3], t0[3];
    #pragma unroll
    for (int i = 0; i < 3; i++) {
        #pragma unroll
        for (int j = 0; j < 3; j++) R0[i][j] = g_pose[i * 4 + j];
        t0[i] = g_pose[i * 4 + 3];
    }
    float R1[3][3], t1[3];
    #pragma unroll
    for (int i = 0; i < 3; i++) {
        #pragma unroll
        for (int j = 0; j < 3; j++)
            R1[i][j] = dR[i][0] * R0[0][j] + dR[i][1] * R0[1][j] + dR[i][2] * R0[2][j];
        t1[i] = dR[i][0] * t0[0] + dR[i][1] * t0[1] + dR[i][2] * t0[2] + dt[i];
    }
    #pragma unroll
    for (int i = 0; i < 3; i++) {
        #pragma unroll
        for (int j = 0; j < 3; j++) g_pose[i * 4 + j] = R1[i][j];
        g_pose[i * 4 + 3] = t1[i];
    }
    if (iter == 2) {
        for (int i = 0; i < 16; i++) outp[i] = g_pose[i];
    }
}

// ---- streaming bilinear corner accumulation ----
struct Blend {
    float nwx, nwy, nwz;
    float w1r, w1g, w1b;
    float s0, s1d, t0, t1;
};
__device__ __forceinline__ void blend_corner(Blend& B, const uint4 q, float w,
                                             bool col0, bool row0) {
    float2 axy = __half22float2(u_as_h2(q.x));
    float2 ezr = __half22float2(u_as_h2(q.y));
    float  d   = __uint_as_float(q.z);
    float2 gb  = __half22float2(u_as_h2(q.w));
    B.nwx += w * axy.x;  B.nwy += w * axy.y;  B.nwz += w * ezr.x;
    B.w1r += w * ezr.y;  B.w1g += w * gb.x;   B.w1b += w * gb.y;
    float wd = w * d;
    if (col0) B.s0 += wd; else B.s1d += wd;
    if (row0) B.t0 += wd; else B.t1 += wd;
}

// ---- fused ICP + RGB accumulation: R15 body, grid-stride over warp-chunks -----------
__global__ void __launch_bounds__(256, 3)
k_accum(const float* __restrict__ d0, const float* __restrict__ Km, int iter,
        float* __restrict__ outp) {
    float fx = Km[0], fy = Km[4], cx = Km[2], cy = Km[5];
    float ifx = 1.f / fx, ify = 1.f / fy;
    float p00 = g_pose[0],  p01 = g_pose[1],  p02 = g_pose[2],  p03 = g_pose[3];
    float p10 = g_pose[4],  p11 = g_pose[5],  p12 = g_pose[6],  p13 = g_pose[7];
    float p20 = g_pose[8],  p21 = g_pose[9],  p22 = g_pose[10], p23 = g_pose[11];

    float acc[27];
    #pragma unroll
    for (int i = 0; i < 27; i++) acc[i] = 0.f;

    int lane = threadIdx.x & 31;
    int warpGlobal = (blockIdx.x * blockDim.x + threadIdx.x) >> 5;
    int gridWarps = (gridDim.x * blockDim.x) >> 5;

    for (int chunk = warpGlobal; chunk < NCHUNKS; chunk += gridWarps) {
        int pbase = chunk * 128;             // whole chunk in one row (1280 % 128 == 0)
        int r = pbase / WW;
        int cw = pbase - r * WW;
        float diry = ((float)r - cy) * ify;

        float dv[4];
        #pragma unroll
        for (int k = 0; k < 4; k++)
            dv[k] = d0[r * WW + cw + lane + 32 * k];

        #pragma unroll
        for (int k = 0; k < 4; k++) {
            int c = cw + lane + 32 * k;
            int idx = r * WW + c;
            float d0v = dv[k];
            if (!(d0v > 0.f)) continue;

            uint4 pk = g_pack[idx];

            float dirx = ((float)c - cx) * ifx;
            float tx = p00 * (dirx * d0v) + p01 * (diry * d0v) + p02 * d0v + p03;
            float ty = p10 * (dirx * d0v) + p11 * (diry * d0v) + p12 * d0v + p13;
            float tz = p20 * (dirx * d0v) + p21 * (diry * d0v) + p22 * d0v + p23;
            float invz = __fdividef(1.f, tz);
            float uu = tx * invz * fx + cx;
            float vv = ty * invz * fy + cy;
            bool inview = (uu > 0.f) && (uu < (float)(WW - 1)) && (vv > 0.f) && (vv < (float)(HH - 1)) && (tz > 0.f);

            float uc = fminf(fmaxf(uu, 0.f), (float)(WW - 2));
            float vc = fminf(fmaxf(vv, 0.f), (float)(HH - 2));
            float u0f = floorf(uc), v0f = floorf(vc);
            int u0 = (int)u0f, v0 = (int)v0f;
            int i00 = v0 * WW + u0, i10 = i00 + WW;
            uint4 q00 = g_nmx[i00], q01 = g_nmx[i00 + 1];
            uint4 q10 = g_nmx[i10], q11 = g_nmx[i10 + 1];

            float invD = __fdividef(1.f, d0v);
            float Jx[6], Jy[6];
            make_warp_jac(dirx, diry, invD, fx, fy, Jx, Jy);
            float2 h0 = __half22float2(u_as_h2(pk.x));
            float2 h1 = __half22float2(u_as_h2(pk.y));
            float2 h2 = __half22float2(u_as_h2(pk.z));
            float2 h3 = __half22float2(u_as_h2(pk.w));

            if (!inview) {
                float A = h0.x * h0.x + h0.y * h0.y + h1.x * h1.x;
                float B = h0.x * h1.y + h0.y * h2.x + h1.x * h2.y;
                float C = h1.y * h1.y + h2.x * h2.x + h2.y * h2.y;
                int o = 0;
                #pragma unroll
                for (int i = 0; i < 6; i++)
                    #pragma unroll
                    for (int j = i; j < 6; j++) {
                        acc[o] -= L_RGBf * (A * Jx[i] * Jx[j] + B * (Jx[i] * Jy[j] + Jy[i] * Jx[j]) + C * Jy[i] * Jy[j]);
                        o++;
                    }
                continue;
            }

            float wu = uu - u0f, wv = vv - v0f;
            float w00 = (1.f - wu) * (1.f - wv), w01 = wu * (1.f - wv);
            float w10 = (1.f - wu) * wv,        w11 = wu * wv;

            Blend B = {0.f,0.f,0.f, 0.f,0.f,0.f, 0.f,0.f,0.f,0.f};
            blend_corner(B, q00, w00, true,  true);
            blend_corner(B, q01, w01, false, true);
            blend_corner(B, q10, w10, true,  false);
            blend_corner(B, q11, w11, false, false);

            float v1z = B.s0 + B.s1d;
            float v1x = (B.s0 * ((float)u0 - cx) + B.s1d * ((float)(u0 + 1) - cx)) * ifx;
            float v1y = (B.t0 * ((float)v0 - cy) + B.t1 * ((float)(v0 + 1) - cy)) * ify;
            float dfx = tx - v1x, dfy = ty - v1y, dfz = tz - v1z;
            float dist2 = dfx * dfx + dfy * dfy + dfz * dfz;
            if (v1z > 0.f && dist2 < 0.01f) {
                float res = B.nwx * dfx + B.nwy * dfy + B.nwz * dfz;
                float J[6];
                J[0] = ty * B.nwz - tz * B.nwy;
                J[1] = tz * B.nwx - tx * B.nwz;
                J[2] = tx * B.nwy - ty * B.nwx;
                J[3] = B.nwx; J[4] = B.nwy; J[5] = B.nwz;
                float ax = fabsf(res);
                float rho = (ax <= HUBER_Bf) ? ax * ax : 2.f * HUBER_Bf * ax - HUBER_Bf * HUBER_Bf;
                float xs = (ax < 1e-8f) ? 1.f : ax;
                float w = sqrtf(rho + 1e-16f) / xs;
                float w2 = w * w;
                int o = 0;
                #pragma unroll
                for (int i = 0; i < 6; i++) {
                    float wi = w2 * J[i];
                    #pragma unroll
                    for (int j = i; j < 6; j++) acc[o++] += wi * J[j];
                }
                #pragma unroll
                for (int i = 0; i < 6; i++) acc[21 + i] += w2 * J[i] * res;
            }

            float a = L_RGBf * (h0.x * B.w1r + h0.y * B.w1g + h1.x * B.w1b - h3.x);
            float b = L_RGBf * (h1.y * B.w1r + h2.x * B.w1g + h2.y * B.w1b - h3.y);
            #pragma unroll
            for (int i = 0; i < 6; i++) acc[21 + i] += a * Jx[i] + b * Jy[i];
        }
    }

    __shared__ float sred[27][9];
    int wid = threadIdx.x >> 5;
    #pragma unroll
    for (int i = 0; i < 27; i++) {
        float v = acc[i];
        #pragma unroll
        for (int o = 16; o > 0; o >>= 1) v += __shfl_down_sync(0xffffffffu, v, o);
        if (lane == 0) sred[i][wid] = v;
    }
    __syncthreads();
    if (threadIdx.x < 27) {
        float s = 0.f;
        #pragma unroll
        for (int w = 0; w < 8; w++) s += sred[threadIdx.x][w];
        atomicAdd(&g_acc[iter][threadIdx.x], (double)s);
    }

    // ---- last-block-does-solve ----
    __shared__ bool isLast;
    __syncthreads();
    if (threadIdx.x == 0) {
        __threadfence();
        unsigned int v = atomicAdd(&g_ticket[iter], 1u);
        isLast = (v == (unsigned int)(gridDim.x - 1));
    }
    __syncthreads();
    if (isLast && threadIdx.x == 0) {
        __threadfence();
        do_solve(iter, outp);
    }
}

// ---------------- launch ----------------
extern "C" void kernel_launch(void* const* d_in, const int* in_sizes, int n_in,
                              void* d_out, int out_size) {
    const float* pose10 = (const float*)d_in[0];
    const float* depth0 = (const float*)d_in[1];
    const float* depth1 = (const float*)d_in[2];
    const float* x0     = (const float*)d_in[3];
    const float* x1     = (const float*)d_in[4];
    const float* Km     = (const float*)d_in[5];
    float* out = (float*)d_out;

    k_minmax<<<512, 256>>>(depth1, pose10);
    k_pre<<<NPIX / (256 * 4), 256>>>(depth0, depth1, x0, x1, Km);
    for (int it = 0; it < 3; it++)
        k_accum<<<ACC_BLOCKS, 256>>>(depth0, Km, it, out);
}